// round 1
// baseline (speedup 1.0000x reference)
#include <cuda_runtime.h>
#include <math.h>

#define NN 12288
#define EE 393216
#define BB 16

// ---------------- device scratch (no allocations allowed) ----------------
__device__ float    g_ew[EE];
__device__ float    g_degsum[NN];
__device__ int      g_rcnt[NN];
__device__ int      g_roff[NN + 1];
__device__ int      g_rcur[NN];
__device__ int      g_col[EE];
__device__ float    g_w[EE];       // ew * dis[col], pre-multiplied at scatter
__device__ float    g_dis[NN];
__device__ float    g_bufA[NN * 64];
__device__ float    g_bufB[NN * 64];
__device__ float    g_colsum[64];
__device__ float    g_colsq[64];
__device__ float    g_scale[64];
__device__ float    g_shift[64];
__device__ unsigned g_embu[BB * 64];
__device__ float    g_embf[BB * 64];
__device__ float    g_o1[BB * 512];
__device__ float    g_o2[BB * 256];

// ---------------- edge weights + degree histogram ----------------
__global__ void k_edge(const float* __restrict__ ea, const float* __restrict__ we,
                       const float* __restrict__ be, const int* __restrict__ ei) {
    int e = blockIdx.x * blockDim.x + threadIdx.x;
    if (e >= EE) return;
    float v = ea[2 * e] * we[0] + ea[2 * e + 1] * we[1] + be[0];
    float w = 1.0f / (1.0f + expf(-v));
    g_ew[e] = w;
    int r = ei[e];
    atomicAdd(&g_degsum[r], w);
    atomicAdd(&g_rcnt[r], 1);
}

// ---------------- single-block exclusive scan over row counts + dis ----------------
__global__ void k_scan() {
    __shared__ int sd[1024];
    __shared__ int running;
    int tid = threadIdx.x;
    if (tid == 0) running = 0;
    __syncthreads();
    for (int base = 0; base < NN; base += 1024) {
        int i = base + tid;
        int v = g_rcnt[i];
        sd[tid] = v;
        __syncthreads();
        for (int off = 1; off < 1024; off <<= 1) {
            int t = (tid >= off) ? sd[tid - off] : 0;
            __syncthreads();
            sd[tid] += t;
            __syncthreads();
        }
        int excl = sd[tid] - v + running;
        g_roff[i] = excl;
        g_rcur[i] = excl;
        g_dis[i]  = rsqrtf(1.0f + g_degsum[i]);   // deg always >= 1 (self loop)
        __syncthreads();
        if (tid == 0) running += sd[1023];
        __syncthreads();
    }
    if (tid == 0) g_roff[NN] = running;
}

// ---------------- scatter edges into CSR, pre-multiply dis[col] ----------------
__global__ void k_scatter(const int* __restrict__ ei) {
    int e = blockIdx.x * blockDim.x + threadIdx.x;
    if (e >= EE) return;
    int r = ei[e];
    int c = ei[EE + e];
    int p = atomicAdd(&g_rcur[r], 1);
    g_col[p] = c;
    g_w[p]   = g_ew[e] * g_dis[c];
}

// ---------------- SpMM: Y = support @ X, one warp per row ----------------
template <int F>
__global__ void k_spmm(const float* __restrict__ X, float* __restrict__ Y) {
    int gw = (blockIdx.x * blockDim.x + threadIdx.x) >> 5;
    if (gw >= NN) return;
    int lane = threadIdx.x & 31;
    int s = g_roff[gw], t = g_roff[gw + 1];
    constexpr int P = (F + 31) / 32;
    float acc0[P], acc1[P];
#pragma unroll
    for (int p = 0; p < P; p++) { acc0[p] = 0.f; acc1[p] = 0.f; }
    int e = s;
    for (; e + 1 < t; e += 2) {   // 2-way unroll: two independent gather chains
        int   c0 = g_col[e];     float w0 = g_w[e];
        int   c1 = g_col[e + 1]; float w1 = g_w[e + 1];
#pragma unroll
        for (int p = 0; p < P; p++) {
            int f = lane + 32 * p;
            if (f < F) {
                acc0[p] += w0 * X[c0 * F + f];
                acc1[p] += w1 * X[c1 * F + f];
            }
        }
    }
    if (e < t) {
        int c0 = g_col[e]; float w0 = g_w[e];
#pragma unroll
        for (int p = 0; p < P; p++) {
            int f = lane + 32 * p;
            if (f < F) acc0[p] += w0 * X[c0 * F + f];
        }
    }
    float dr = g_dis[gw];
#pragma unroll
    for (int p = 0; p < P; p++) {
        int f = lane + 32 * p;
        if (f < F)
            Y[gw * F + f] = dr * (acc0[p] + acc1[p] + dr * X[gw * F + f]);
    }
}

// ---------------- dense: Z = X @ W + b, with per-column BN stats ----------------
template <int FI, int FO>
__global__ void k_dense(const float* __restrict__ X, const float* __restrict__ W,
                        const float* __restrict__ bias, float* __restrict__ Z) {
    __shared__ float Ws[FI * FO];
    __shared__ float s1[256], s2[256];
    int tid = threadIdx.x;
    for (int i = tid; i < FI * FO; i += 256) Ws[i] = W[i];
    __syncthreads();
    constexpr int NPB = 256 / FO;
    int node = blockIdx.x * NPB + tid / FO;
    int j    = tid % FO;
    float acc = bias[j];
    const float* xr = X + node * FI;
#pragma unroll
    for (int k = 0; k < FI; k++) acc += xr[k] * Ws[k * FO + j];
    Z[node * FO + j] = acc;
    s1[tid] = acc; s2[tid] = acc * acc;
    __syncthreads();
#pragma unroll
    for (int st = 128; st >= FO; st >>= 1) {
        if (tid < st) { s1[tid] += s1[tid + st]; s2[tid] += s2[tid + st]; }
        __syncthreads();
    }
    if (tid < FO) {
        atomicAdd(&g_colsum[tid], s1[tid]);
        atomicAdd(&g_colsq[tid],  s2[tid]);
    }
}

// ---------------- BN finalize: scale/shift per column ----------------
__global__ void k_bnfin(const float* __restrict__ g, const float* __restrict__ be, int F) {
    int j = threadIdx.x;
    if (j >= F) return;
    float mu  = g_colsum[j] * (1.0f / NN);
    float var = g_colsq[j]  * (1.0f / NN) - mu * mu;
    float sc  = g[j] * rsqrtf(var + 1e-5f);
    g_scale[j] = sc;
    g_shift[j] = be[j] - mu * sc;
}

// ---------------- BN apply + ReLU (in place) ----------------
__global__ void k_bnrelu(float* __restrict__ Z, int mask) {
    int i = blockIdx.x * blockDim.x + threadIdx.x;
    int j = i & mask;
    float v = g_scale[j] * Z[i] + g_shift[j];
    Z[i] = v > 0.f ? v : 0.f;
}

// ---------------- per-graph max pool (post-ReLU values >= 0 -> uint atomicMax) ----------------
__global__ void k_segmax(const float* __restrict__ H, const int* __restrict__ batch) {
    int i = blockIdx.x * blockDim.x + threadIdx.x;
    if (i >= NN * 64) return;
    int node = i >> 6, f = i & 63;
    int b = batch[node];
    atomicMax(&g_embu[b * 64 + f], __float_as_uint(H[i]));
}

__global__ void k_embout(float* __restrict__ out, int out_size) {
    int i = blockIdx.x * blockDim.x + threadIdx.x;
    if (i >= BB * 64) return;
    float v = __uint_as_float(g_embu[i]);
    g_embf[i] = v;
    int o = BB * 11 + i;
    if (o < out_size) out[o] = v;
}

// ---------------- MLP layer with local BN (16 rows owned per column-thread) ----------------
template <int FI, int FO>
__global__ void k_mlp(const float* __restrict__ X, const float* __restrict__ W,
                      const float* __restrict__ bias, const float* __restrict__ gam,
                      const float* __restrict__ bet, float* __restrict__ Y) {
    __shared__ float Xs[BB * FI];
    for (int i = threadIdx.x; i < BB * FI; i += blockDim.x) Xs[i] = X[i];
    __syncthreads();
    int j = blockIdx.x * blockDim.x + threadIdx.x;
    if (j >= FO) return;
    float acc[BB];
    float b = bias[j];
#pragma unroll
    for (int r = 0; r < BB; r++) acc[r] = b;
    for (int k = 0; k < FI; k++) {
        float w = W[k * FO + j];
#pragma unroll
        for (int r = 0; r < BB; r++) acc[r] += Xs[r * FI + k] * w;
    }
    float s = 0.f, sq = 0.f;
#pragma unroll
    for (int r = 0; r < BB; r++) { s += acc[r]; sq += acc[r] * acc[r]; }
    float mu  = s  * (1.0f / BB);
    float var = sq * (1.0f / BB) - mu * mu;
    float sc  = gam[j] * rsqrtf(var + 1e-5f);
    float sh  = bet[j] - mu * sc;
#pragma unroll
    for (int r = 0; r < BB; r++) {
        float v = sc * acc[r] + sh;
        Y[r * FO + j] = v > 0.f ? v : 0.f;
    }
}

// ---------------- final linear + log_softmax ----------------
__global__ void k_head(const float* __restrict__ X, const float* __restrict__ W,
                       const float* __restrict__ bias, float* __restrict__ out, int out_size) {
    __shared__ float L[BB * 11];
    __shared__ float mrow[BB], lrow[BB];
    int tid = threadIdx.x;
    if (tid < BB * 11) {
        int r = tid / 11, c = tid % 11;
        float acc = bias[c];
        for (int k = 0; k < 256; k++) acc += X[r * 256 + k] * W[k * 11 + c];
        L[tid] = acc;
    }
    __syncthreads();
    if (tid < BB) {
        float m = -1e30f;
        for (int c = 0; c < 11; c++) m = fmaxf(m, L[tid * 11 + c]);
        float s = 0.f;
        for (int c = 0; c < 11; c++) s += expf(L[tid * 11 + c] - m);
        mrow[tid] = m; lrow[tid] = logf(s);
    }
    __syncthreads();
    if (tid < BB * 11 && tid < out_size) {
        int r = tid / 11;
        out[tid] = L[tid] - mrow[r] - lrow[r];
    }
}

// ---------------- launch ----------------
extern "C" void kernel_launch(void* const* d_in, const int* in_sizes, int n_in,
                              void* d_out, int out_size) {
    const float* x    = (const float*)d_in[0];
    const float* ea   = (const float*)d_in[1];
    const float* we   = (const float*)d_in[2];
    const float* be   = (const float*)d_in[3];
    const float* w1   = (const float*)d_in[4];
    const float* b1   = (const float*)d_in[5];
    const float* g1   = (const float*)d_in[6];
    const float* be1  = (const float*)d_in[7];
    const float* w2   = (const float*)d_in[8];
    const float* b2   = (const float*)d_in[9];
    const float* g2   = (const float*)d_in[10];
    const float* be2  = (const float*)d_in[11];
    const float* w3   = (const float*)d_in[12];
    const float* b3   = (const float*)d_in[13];
    const float* g3   = (const float*)d_in[14];
    const float* be3  = (const float*)d_in[15];
    const float* wf1  = (const float*)d_in[16];
    const float* bf1  = (const float*)d_in[17];
    const float* gf1  = (const float*)d_in[18];
    const float* bef1 = (const float*)d_in[19];
    const float* wf2  = (const float*)d_in[20];
    const float* bf2  = (const float*)d_in[21];
    const float* gf2  = (const float*)d_in[22];
    const float* bef2 = (const float*)d_in[23];
    const float* wf3  = (const float*)d_in[24];
    const float* bf3  = (const float*)d_in[25];
    const int*   ei   = (const int*)d_in[26];
    const int*   batch= (const int*)d_in[27];
    float* out = (float*)d_out;

    void *p_degsum, *p_rcnt, *p_colsum, *p_colsq, *p_embu;
    void *p_bufA, *p_bufB, *p_embf, *p_o1, *p_o2;
    cudaGetSymbolAddress(&p_degsum, g_degsum);
    cudaGetSymbolAddress(&p_rcnt,   g_rcnt);
    cudaGetSymbolAddress(&p_colsum, g_colsum);
    cudaGetSymbolAddress(&p_colsq,  g_colsq);
    cudaGetSymbolAddress(&p_embu,   g_embu);
    cudaGetSymbolAddress(&p_bufA,   g_bufA);
    cudaGetSymbolAddress(&p_bufB,   g_bufB);
    cudaGetSymbolAddress(&p_embf,   g_embf);
    cudaGetSymbolAddress(&p_o1,     g_o1);
    cudaGetSymbolAddress(&p_o2,     g_o2);
    float* bufA = (float*)p_bufA;
    float* bufB = (float*)p_bufB;

    // --- graph build ---
    cudaMemsetAsync(p_degsum, 0, NN * sizeof(float));
    cudaMemsetAsync(p_rcnt,   0, NN * sizeof(int));
    k_edge<<<EE / 256, 256>>>(ea, we, be, ei);
    k_scan<<<1, 1024>>>();
    k_scatter<<<EE / 256, 256>>>(ei);

    // --- GCN layer 1: SpMM(x,15) -> dense 15->32 -> BN -> ReLU ---
    k_spmm<15><<<NN / 8, 256>>>(x, bufA);
    cudaMemsetAsync(p_colsum, 0, 64 * sizeof(float));
    cudaMemsetAsync(p_colsq,  0, 64 * sizeof(float));
    k_dense<15, 32><<<NN / 8, 256>>>(bufA, w1, b1, bufB);
    k_bnfin<<<1, 64>>>(g1, be1, 32);
    k_bnrelu<<<NN * 32 / 256, 256>>>(bufB, 31);

    // --- GCN layer 2: SpMM(32) -> dense 32->64 -> BN -> ReLU ---
    k_spmm<32><<<NN / 8, 256>>>(bufB, bufA);
    cudaMemsetAsync(p_colsum, 0, 64 * sizeof(float));
    cudaMemsetAsync(p_colsq,  0, 64 * sizeof(float));
    k_dense<32, 64><<<NN / 4, 256>>>(bufA, w2, b2, bufB);
    k_bnfin<<<1, 64>>>(g2, be2, 64);
    k_bnrelu<<<NN * 64 / 256, 256>>>(bufB, 63);

    // --- GCN layer 3: SpMM(64) -> dense 64->64 -> BN -> ReLU ---
    k_spmm<64><<<NN / 8, 256>>>(bufB, bufA);
    cudaMemsetAsync(p_colsum, 0, 64 * sizeof(float));
    cudaMemsetAsync(p_colsq,  0, 64 * sizeof(float));
    k_dense<64, 64><<<NN / 4, 256>>>(bufA, w3, b3, bufB);
    k_bnfin<<<1, 64>>>(g3, be3, 64);
    k_bnrelu<<<NN * 64 / 256, 256>>>(bufB, 63);

    // --- global max pool ---
    cudaMemsetAsync(p_embu, 0, BB * 64 * sizeof(unsigned));
    k_segmax<<<NN * 64 / 256, 256>>>(bufB, batch);
    k_embout<<<4, 256>>>(out, out_size);

    // --- MLP head ---
    k_mlp<64, 512><<<4, 128>>>((float*)p_embf, wf1, bf1, gf1, bef1, (float*)p_o1);
    k_mlp<512, 256><<<2, 128>>>((float*)p_o1, wf2, bf2, gf2, bef2, (float*)p_o2);
    k_head<<<1, 192>>>((float*)p_o2, wf3, bf3, out, out_size);
}

// round 6
// speedup vs baseline: 1.8464x; 1.8464x over previous
#include <cuda_runtime.h>
#include <math.h>

#define NN 12288
#define EE 393216
#define BB 16
#define CAP 96
#define INVN (1.0f/12288.0f)

// ---------------- device scratch ----------------
__device__ int2     g_cw[NN * CAP];                    // (col, ew bits) padded CSR
__device__ unsigned g_zb[2 * NN + 384 + BB * 64];      // degsum | cnt | stats(6x64) | embu
__device__ float    g_dis[NN];
__device__ float    g_bufA[NN * 64];
__device__ float    g_bufB[NN * 64];
__device__ float    g_o1[BB * 512];
__device__ float    g_o2[BB * 256];

// ---------------- edge weights + direct padded-CSR scatter ----------------
__global__ void __launch_bounds__(256) k_edge(const float* __restrict__ ea,
                                              const float* __restrict__ we,
                                              const float* __restrict__ be,
                                              const int* __restrict__ ei,
                                              float* __restrict__ degsum,
                                              int* __restrict__ cnt) {
    int e = blockIdx.x * 256 + threadIdx.x;
    if (e >= EE) return;
    float2 a = ((const float2*)ea)[e];
    float v = fmaf(a.x, __ldg(we), fmaf(a.y, __ldg(we + 1), __ldg(be)));
    float w = 1.0f / (1.0f + __expf(-v));
    int r = ei[e];
    int c = ei[EE + e];
    atomicAdd(&degsum[r], w);
    int p = atomicAdd(&cnt[r], 1);
    if (p < CAP) g_cw[r * CAP + p] = make_int2(c, __float_as_int(w));
}

// ---------------- x @ w1 (15->32, no bias: BN-invariant) + dis ----------------
__global__ void __launch_bounds__(256) k_xw1(const float* __restrict__ x,
                                             const float* __restrict__ w1,
                                             const float* __restrict__ degsum) {
    __shared__ float Ws[15 * 32];
    int tid = threadIdx.x;
    for (int i = tid; i < 15 * 32; i += 256) Ws[i] = w1[i];   // FIXED: strided load
    __syncthreads();
    int node = blockIdx.x * 8 + (tid >> 5);
    int j = tid & 31;
    const float* xr = x + node * 15;
    float acc = 0.f;
#pragma unroll
    for (int k = 0; k < 15; k++) acc = fmaf(__ldg(xr + k), Ws[k * 32 + j], acc);
    g_bufA[node * 32 + j] = acc;
    if (tid < 8) {
        int r = blockIdx.x * 8 + tid;
        g_dis[r] = rsqrtf(1.0f + degsum[r]);
    }
}

// ---------------- SpMM: Y = support @ T(X), warp/row, float4 + multi chains ----------
// LOADBN: apply scale/shift(+relu) computed from bnst/gamma/beta to every X load.
// STATS:  emit per-column sum/sumsq of Y into stout (sum@0, sq@64).
template <int F, bool LOADBN, bool STATS>
__global__ void __launch_bounds__(256) k_spmm(const float* __restrict__ X,
                                              float* __restrict__ Y,
                                              const int* __restrict__ cnt,
                                              const float* __restrict__ bnst,
                                              const float* __restrict__ gamma,
                                              const float* __restrict__ beta,
                                              float* __restrict__ stout) {
    constexpr int FQ = F / 4;          // lanes covering the feature row (float4 each)
    constexpr int G = 32 / FQ;         // parallel edge groups per warp
    __shared__ float s_sum[64], s_sq[64];
    int tid = threadIdx.x;
    if (STATS) {
        if (tid < 64) { s_sum[tid] = 0.f; s_sq[tid] = 0.f; }
        __syncthreads();
    }
    int lane = tid & 31;
    int q = lane & (FQ - 1);
    int g = lane / FQ;
    int r = blockIdx.x * 8 + (tid >> 5);

    float4 sc, sh;
    if (LOADBN) {
        float4 su = *(const float4*)(bnst + 4 * q);
        float4 sq = *(const float4*)(bnst + 64 + 4 * q);
        float4 ga = *(const float4*)(gamma + 4 * q);
        float4 bb = *(const float4*)(beta + 4 * q);
        float mx = su.x * INVN, my = su.y * INVN, mz = su.z * INVN, mw = su.w * INVN;
        sc.x = ga.x * rsqrtf(sq.x * INVN - mx * mx + 1e-5f);
        sc.y = ga.y * rsqrtf(sq.y * INVN - my * my + 1e-5f);
        sc.z = ga.z * rsqrtf(sq.z * INVN - mz * mz + 1e-5f);
        sc.w = ga.w * rsqrtf(sq.w * INVN - mw * mw + 1e-5f);
        sh.x = fmaf(-mx, sc.x, bb.x);
        sh.y = fmaf(-my, sc.y, bb.y);
        sh.z = fmaf(-mz, sc.z, bb.z);
        sh.w = fmaf(-mw, sc.w, bb.w);
    }

    const float4* X4 = (const float4*)X;
    auto proc = [&](int e, float4& a) {
        int2 cw = g_cw[e];
        float w = __int_as_float(cw.y) * g_dis[cw.x];
        float4 xv = X4[cw.x * FQ + q];
        if (LOADBN) {
            xv.x = fmaxf(0.f, fmaf(sc.x, xv.x, sh.x));
            xv.y = fmaxf(0.f, fmaf(sc.y, xv.y, sh.y));
            xv.z = fmaxf(0.f, fmaf(sc.z, xv.z, sh.z));
            xv.w = fmaxf(0.f, fmaf(sc.w, xv.w, sh.w));
        }
        a.x = fmaf(w, xv.x, a.x);
        a.y = fmaf(w, xv.y, a.y);
        a.z = fmaf(w, xv.z, a.z);
        a.w = fmaf(w, xv.w, a.w);
    };

    int n = min(cnt[r], CAP);
    int base = r * CAP;
    float4 a0 = {0, 0, 0, 0}, a1 = a0, a2 = a0, a3 = a0;
    int k = g;
    for (; k + 3 * G < n; k += 4 * G) {
        proc(base + k, a0);
        proc(base + k + G, a1);
        proc(base + k + 2 * G, a2);
        proc(base + k + 3 * G, a3);
    }
    for (; k < n; k += G) proc(base + k, a0);

    float4 acc;
    acc.x = (a0.x + a1.x) + (a2.x + a3.x);
    acc.y = (a0.y + a1.y) + (a2.y + a3.y);
    acc.z = (a0.z + a1.z) + (a2.z + a3.z);
    acc.w = (a0.w + a1.w) + (a2.w + a3.w);
#pragma unroll
    for (int off = FQ; off < 32; off <<= 1) {
        acc.x += __shfl_xor_sync(0xffffffffu, acc.x, off);
        acc.y += __shfl_xor_sync(0xffffffffu, acc.y, off);
        acc.z += __shfl_xor_sync(0xffffffffu, acc.z, off);
        acc.w += __shfl_xor_sync(0xffffffffu, acc.w, off);
    }
    if (g == 0) {
        float dr = g_dis[r];
        float4 xr = X4[r * FQ + q];
        if (LOADBN) {
            xr.x = fmaxf(0.f, fmaf(sc.x, xr.x, sh.x));
            xr.y = fmaxf(0.f, fmaf(sc.y, xr.y, sh.y));
            xr.z = fmaxf(0.f, fmaf(sc.z, xr.z, sh.z));
            xr.w = fmaxf(0.f, fmaf(sc.w, xr.w, sh.w));
        }
        float4 v;
        v.x = dr * fmaf(dr, xr.x, acc.x);
        v.y = dr * fmaf(dr, xr.y, acc.y);
        v.z = dr * fmaf(dr, xr.z, acc.z);
        v.w = dr * fmaf(dr, xr.w, acc.w);
        ((float4*)Y)[r * FQ + q] = v;
        if (STATS) {
            atomicAdd(&s_sum[4 * q + 0], v.x);
            atomicAdd(&s_sum[4 * q + 1], v.y);
            atomicAdd(&s_sum[4 * q + 2], v.z);
            atomicAdd(&s_sum[4 * q + 3], v.w);
            atomicAdd(&s_sq[4 * q + 0], v.x * v.x);
            atomicAdd(&s_sq[4 * q + 1], v.y * v.y);
            atomicAdd(&s_sq[4 * q + 2], v.z * v.z);
            atomicAdd(&s_sq[4 * q + 3], v.w * v.w);
        }
    }
    if (STATS) {
        __syncthreads();
        if (tid < F) {
            atomicAdd(&stout[tid], s_sum[tid]);
            atomicAdd(&stout[64 + tid], s_sq[tid]);
        }
    }
}

// ---------------- dense: Z = X @ W (no bias), with per-column BN stats ----------------
template <int FI, int FO>
__global__ void __launch_bounds__(256) k_dense(const float* __restrict__ X,
                                               const float* __restrict__ W,
                                               float* __restrict__ Z,
                                               float* __restrict__ stout) {
    __shared__ float Ws[FI * FO];
    __shared__ float s1[256], s2[256];
    int tid = threadIdx.x;
    for (int i = tid; i < FI * FO; i += 256) Ws[i] = W[i];
    __syncthreads();
    constexpr int NPB = 256 / FO;
    int node = blockIdx.x * NPB + tid / FO;
    int j = tid % FO;
    const float* xr = X + node * FI;
    float acc = 0.f;
#pragma unroll
    for (int k = 0; k < FI; k++) acc = fmaf(__ldg(xr + k), Ws[k * FO + j], acc);
    Z[node * FO + j] = acc;
    s1[tid] = acc;
    s2[tid] = acc * acc;
    __syncthreads();
#pragma unroll
    for (int st = 128; st >= FO; st >>= 1) {
        if (tid < st) { s1[tid] += s1[tid + st]; s2[tid] += s2[tid + st]; }
        __syncthreads();
    }
    if (tid < FO) {
        atomicAdd(&stout[tid], s1[tid]);
        atomicAdd(&stout[64 + tid], s2[tid]);
    }
}

// ---------------- BN3 + ReLU + per-graph max pool, fused ----------------
__global__ void __launch_bounds__(256) k_pool(const float* __restrict__ Z,
                                              const int* __restrict__ batch,
                                              const float* __restrict__ bnst,
                                              const float* __restrict__ gamma,
                                              const float* __restrict__ beta,
                                              unsigned* __restrict__ embu) {
    int i = blockIdx.x * 256 + threadIdx.x;
    int f = i & 63, node = i >> 6;
    float su = bnst[f], sq = bnst[64 + f];
    float mu = su * INVN;
    float scv = gamma[f] * rsqrtf(sq * INVN - mu * mu + 1e-5f);
    float shv = fmaf(-mu, scv, beta[f]);
    float v = fmaxf(0.f, fmaf(scv, Z[i], shv));
    atomicMax(&embu[batch[node] * 64 + f], __float_as_uint(v));
}

// ---------------- MLP layer: (r,j)-parallel, shuffle BN over 16 rows ----------------
template <int FI, int FO, bool CVT>
__global__ void __launch_bounds__(256) k_mlp(const void* __restrict__ Xin,
                                             const float* __restrict__ W,
                                             const float* __restrict__ gamma,
                                             const float* __restrict__ beta,
                                             float* __restrict__ Y,
                                             float* __restrict__ out, int out_size) {
    __shared__ float Xs[BB * FI];
    int tid = threadIdx.x;
    for (int i = tid; i < BB * FI; i += 256) {
        float v = CVT ? __uint_as_float(((const unsigned*)Xin)[i]) : ((const float*)Xin)[i];
        Xs[i] = v;
        if (CVT && blockIdx.x == 0) {
            int o = BB * 11 + i;
            if (o < out_size) out[o] = v;   // emb output
        }
    }
    __syncthreads();
    int r = tid & 15;
    int jl = tid >> 4;
    int j = blockIdx.x * 16 + jl;
    float acc = 0.f;
    for (int k = 0; k < FI; k++) acc = fmaf(Xs[r * FI + k], __ldg(W + k * FO + j), acc);
    float s = acc, s2 = acc * acc;
#pragma unroll
    for (int off = 1; off < 16; off <<= 1) {
        s  += __shfl_xor_sync(0xffffffffu, s, off);
        s2 += __shfl_xor_sync(0xffffffffu, s2, off);
    }
    float mu = s * (1.0f / BB);
    float var = s2 * (1.0f / BB) - mu * mu;
    float scv = gamma[j] * rsqrtf(var + 1e-5f);
    float shv = fmaf(-mu, scv, beta[j]);
    Y[r * FO + j] = fmaxf(0.f, fmaf(scv, acc, shv));
}

// ---------------- final linear + log_softmax ----------------
__global__ void k_head(const float* __restrict__ X, const float* __restrict__ W,
                       const float* __restrict__ bias, float* __restrict__ out, int out_size) {
    __shared__ float L[BB * 11];
    __shared__ float mrow[BB], lrow[BB];
    int tid = threadIdx.x;
    if (tid < BB * 11) {
        int r = tid / 11, c = tid % 11;
        float acc = bias[c];
        for (int k = 0; k < 256; k++) acc = fmaf(X[r * 256 + k], __ldg(W + k * 11 + c), acc);
        L[tid] = acc;
    }
    __syncthreads();
    if (tid < BB) {
        float m = -1e30f;
        for (int c = 0; c < 11; c++) m = fmaxf(m, L[tid * 11 + c]);
        float s = 0.f;
        for (int c = 0; c < 11; c++) s += expf(L[tid * 11 + c] - m);
        mrow[tid] = m;
        lrow[tid] = logf(s);
    }
    __syncthreads();
    if (tid < BB * 11 && tid < out_size) {
        int r = tid / 11;
        out[tid] = L[tid] - mrow[r] - lrow[r];
    }
}

// ---------------- launch ----------------
extern "C" void kernel_launch(void* const* d_in, const int* in_sizes, int n_in,
                              void* d_out, int out_size) {
    const float* x    = (const float*)d_in[0];
    const float* ea   = (const float*)d_in[1];
    const float* we   = (const float*)d_in[2];
    const float* be   = (const float*)d_in[3];
    const float* w1   = (const float*)d_in[4];
    const float* g1   = (const float*)d_in[6];
    const float* be1  = (const float*)d_in[7];
    const float* w2   = (const float*)d_in[8];
    const float* g2   = (const float*)d_in[10];
    const float* be2  = (const float*)d_in[11];
    const float* w3   = (const float*)d_in[12];
    const float* g3   = (const float*)d_in[14];
    const float* be3  = (const float*)d_in[15];
    const float* wf1  = (const float*)d_in[16];
    const float* gf1  = (const float*)d_in[18];
    const float* bef1 = (const float*)d_in[19];
    const float* wf2  = (const float*)d_in[20];
    const float* gf2  = (const float*)d_in[22];
    const float* bef2 = (const float*)d_in[23];
    const float* wf3  = (const float*)d_in[24];
    const float* bf3  = (const float*)d_in[25];
    const int*   ei   = (const int*)d_in[26];
    const int*   batch= (const int*)d_in[27];
    float* out = (float*)d_out;

    void *pz, *pa, *pb, *po1, *po2;
    cudaGetSymbolAddress(&pz, g_zb);
    cudaGetSymbolAddress(&pa, g_bufA);
    cudaGetSymbolAddress(&pb, g_bufB);
    cudaGetSymbolAddress(&po1, g_o1);
    cudaGetSymbolAddress(&po2, g_o2);
    unsigned* zb = (unsigned*)pz;
    float* degsum = (float*)zb;
    int* cnt = (int*)(zb + NN);
    float* stats = (float*)(zb + 2 * NN);          // S1@0, S2@128, S3@256 (sum@+0, sq@+64)
    unsigned* embu = zb + 2 * NN + 384;
    float* bufA = (float*)pa;
    float* bufB = (float*)pb;
    float* o1 = (float*)po1;
    float* o2 = (float*)po2;

    cudaMemsetAsync(pz, 0, sizeof(unsigned) * (2 * NN + 384 + BB * 64));
    k_edge<<<EE / 256, 256>>>(ea, we, be, ei, degsum, cnt);
    k_xw1<<<NN / 8, 256>>>(x, w1, degsum);
    // layer 1: spmm over x@w1, emit BN1 stats
    k_spmm<32, false, true><<<NN / 8, 256>>>(bufA, bufB, cnt, nullptr, nullptr, nullptr, stats);
    // layer 2: spmm applies BN1+relu on load; dense 32->64 emits BN2 stats
    k_spmm<32, true, false><<<NN / 8, 256>>>(bufB, bufA, cnt, stats, g1, be1, nullptr);
    k_dense<32, 64><<<NN / 4, 256>>>(bufA, w2, bufB, stats + 128);
    // layer 3: spmm applies BN2+relu on load; dense 64->64 emits BN3 stats
    k_spmm<64, true, false><<<NN / 8, 256>>>(bufB, bufA, cnt, stats + 128, g2, be2, nullptr);
    k_dense<64, 64><<<NN / 4, 256>>>(bufA, w3, bufB, stats + 256);
    // BN3 + relu + global max pool
    k_pool<<<NN * 64 / 256, 256>>>(bufB, batch, stats + 256, g3, be3, embu);
    // MLP head (emb conversion + emb output fused into mlp1)
    k_mlp<64, 512, true><<<32, 256>>>(embu, wf1, gf1, bef1, o1, out, out_size);
    k_mlp<512, 256, false><<<16, 256>>>(o1, wf2, gf2, bef2, o2, out, out_size);
    k_head<<<1, 192>>>(o2, wf3, bf3, out, out_size);
}

// round 9
// speedup vs baseline: 2.0844x; 1.1289x over previous
#include <cuda_runtime.h>
#include <math.h>

#define NN 12288
#define EE 393216
#define BB 16
#define CAP 96
#define INVN (1.0f/12288.0f)

// ---------------- device scratch ----------------
__device__ int2     g_cw[NN * CAP];                    // (col, ew bits) padded CSR
__device__ unsigned g_zb[2 * NN + 384 + BB * 64];      // degsum | cnt | stats(6x64) | embu
__device__ float    g_dis[NN];
__device__ float    g_bufA[NN * 64];
__device__ float    g_bufB[NN * 64];
__device__ float    g_o1[BB * 512];
__device__ float    g_o2[BB * 256];

// ---------------- fused: edge weights + padded-CSR scatter  |  x@w1 ----------------
__global__ void __launch_bounds__(256) k_edgexw1(const float* __restrict__ ea,
                                                 const float* __restrict__ we,
                                                 const float* __restrict__ be,
                                                 const int* __restrict__ ei,
                                                 const float* __restrict__ x,
                                                 const float* __restrict__ w1,
                                                 float* __restrict__ degsum,
                                                 int* __restrict__ cnt) {
    if (blockIdx.x < EE / 256) {
        int e = blockIdx.x * 256 + threadIdx.x;
        float2 a = ((const float2*)ea)[e];
        float v = fmaf(a.x, __ldg(we), fmaf(a.y, __ldg(we + 1), __ldg(be)));
        float w = 1.0f / (1.0f + __expf(-v));
        int r = ei[e];
        int c = ei[EE + e];
        atomicAdd(&degsum[r], w);
        int p = atomicAdd(&cnt[r], 1);
        if (p < CAP) g_cw[r * CAP + p] = make_int2(c, __float_as_int(w));
    } else {
        __shared__ float Ws[15 * 32];
        int tid = threadIdx.x;
        for (int i = tid; i < 15 * 32; i += 256) Ws[i] = w1[i];
        __syncthreads();
        int node = (blockIdx.x - EE / 256) * 8 + (tid >> 5);
        int j = tid & 31;
        const float* xr = x + node * 15;
        float acc = 0.f;
#pragma unroll
        for (int k = 0; k < 15; k++) acc = fmaf(__ldg(xr + k), Ws[k * 32 + j], acc);
        g_bufA[node * 32 + j] = acc;
    }
}

// ---------------- dis = rsqrt(1 + degsum) ----------------
__global__ void __launch_bounds__(256) k_dis(const float* __restrict__ degsum) {
    int i = blockIdx.x * 256 + threadIdx.x;
    g_dis[i] = rsqrtf(1.0f + degsum[i]);
}

// ---------------- spmm layer1 (F=32): stats out + premultiply dis[col] into weights ----
__global__ void __launch_bounds__(256) k_spmm1(const float* __restrict__ X,
                                               float* __restrict__ Y,
                                               const int* __restrict__ cnt,
                                               float* __restrict__ stout) {
    // F=32: FQ=8 lanes per feature row, G=4 edge groups
    __shared__ float s_sum[64], s_sq[64];
    int tid = threadIdx.x;
    if (tid < 64) { s_sum[tid] = 0.f; s_sq[tid] = 0.f; }
    __syncthreads();
    int lane = tid & 31;
    int q = lane & 7;
    int g = lane >> 3;
    int r = blockIdx.x * 8 + (tid >> 5);

    const float4* X4 = (const float4*)X;
    auto proc = [&](int e, float4& a) {
        int2 cw = g_cw[e];
        float w = __int_as_float(cw.y) * g_dis[cw.x];
        if (q == 0) g_cw[e].y = __float_as_int(w);   // writeback premultiplied weight
        float4 xv = X4[cw.x * 8 + q];
        a.x = fmaf(w, xv.x, a.x);
        a.y = fmaf(w, xv.y, a.y);
        a.z = fmaf(w, xv.z, a.z);
        a.w = fmaf(w, xv.w, a.w);
    };

    int n = min(cnt[r], CAP);
    int base = r * CAP;
    float4 a0 = {0, 0, 0, 0}, a1 = a0, a2 = a0, a3 = a0;
    int k = g;
    for (; k + 12 < n; k += 16) {
        proc(base + k, a0);
        proc(base + k + 4, a1);
        proc(base + k + 8, a2);
        proc(base + k + 12, a3);
    }
    for (; k < n; k += 4) proc(base + k, a0);

    float4 acc;
    acc.x = (a0.x + a1.x) + (a2.x + a3.x);
    acc.y = (a0.y + a1.y) + (a2.y + a3.y);
    acc.z = (a0.z + a1.z) + (a2.z + a3.z);
    acc.w = (a0.w + a1.w) + (a2.w + a3.w);
#pragma unroll
    for (int off = 8; off < 32; off <<= 1) {
        acc.x += __shfl_xor_sync(0xffffffffu, acc.x, off);
        acc.y += __shfl_xor_sync(0xffffffffu, acc.y, off);
        acc.z += __shfl_xor_sync(0xffffffffu, acc.z, off);
        acc.w += __shfl_xor_sync(0xffffffffu, acc.w, off);
    }
    if (g == 0) {
        float dr = g_dis[r];
        float4 xr = X4[r * 8 + q];
        float4 v;
        v.x = dr * fmaf(dr, xr.x, acc.x);
        v.y = dr * fmaf(dr, xr.y, acc.y);
        v.z = dr * fmaf(dr, xr.z, acc.z);
        v.w = dr * fmaf(dr, xr.w, acc.w);
        ((float4*)Y)[r * 8 + q] = v;
        atomicAdd(&s_sum[4 * q + 0], v.x);
        atomicAdd(&s_sum[4 * q + 1], v.y);
        atomicAdd(&s_sum[4 * q + 2], v.z);
        atomicAdd(&s_sum[4 * q + 3], v.w);
        atomicAdd(&s_sq[4 * q + 0], v.x * v.x);
        atomicAdd(&s_sq[4 * q + 1], v.y * v.y);
        atomicAdd(&s_sq[4 * q + 2], v.z * v.z);
        atomicAdd(&s_sq[4 * q + 3], v.w * v.w);
    }
    __syncthreads();
    if (tid < 32) {
        atomicAdd(&stout[tid], s_sum[tid]);
        atomicAdd(&stout[64 + tid], s_sq[tid]);
    }
}

// ---------------- fused spmm (BN+relu on load) + dense FI->64 + stats ----------------
template <int FI>
__global__ void __launch_bounds__(256) k_sd(const float* __restrict__ X,
                                            const float* __restrict__ W,
                                            float* __restrict__ Z,
                                            const int* __restrict__ cnt,
                                            const float* __restrict__ bnst,
                                            const float* __restrict__ gamma,
                                            const float* __restrict__ beta,
                                            float* __restrict__ stout) {
    constexpr int FQ = FI / 4;
    constexpr int G = 32 / FQ;
    __shared__ float Ws[FI * 64];
    __shared__ float s_sum[64], s_sq[64];
    int tid = threadIdx.x;
    for (int i = tid; i < FI * 64; i += 256) Ws[i] = W[i];
    if (tid < 64) { s_sum[tid] = 0.f; s_sq[tid] = 0.f; }
    __syncthreads();
    int lane = tid & 31;
    int q = lane & (FQ - 1);
    int g = lane / FQ;
    int r = blockIdx.x * 8 + (tid >> 5);

    // BN scale/shift for the previous layer (feats 4q..4q+3)
    float4 sc, sh;
    {
        float4 su = *(const float4*)(bnst + 4 * q);
        float4 sq = *(const float4*)(bnst + 64 + 4 * q);
        float4 ga = *(const float4*)(gamma + 4 * q);
        float4 bb = *(const float4*)(beta + 4 * q);
        float mx = su.x * INVN, my = su.y * INVN, mz = su.z * INVN, mw = su.w * INVN;
        sc.x = ga.x * rsqrtf(sq.x * INVN - mx * mx + 1e-5f);
        sc.y = ga.y * rsqrtf(sq.y * INVN - my * my + 1e-5f);
        sc.z = ga.z * rsqrtf(sq.z * INVN - mz * mz + 1e-5f);
        sc.w = ga.w * rsqrtf(sq.w * INVN - mw * mw + 1e-5f);
        sh.x = fmaf(-mx, sc.x, bb.x);
        sh.y = fmaf(-my, sc.y, bb.y);
        sh.z = fmaf(-mz, sc.z, bb.z);
        sh.w = fmaf(-mw, sc.w, bb.w);
    }

    const float4* X4 = (const float4*)X;
    auto proc = [&](int e, float4& a) {
        int2 cw = g_cw[e];                      // weight already premultiplied by dis[col]
        float w = __int_as_float(cw.y);
        float4 xv = X4[cw.x * FQ + q];
        xv.x = fmaxf(0.f, fmaf(sc.x, xv.x, sh.x));
        xv.y = fmaxf(0.f, fmaf(sc.y, xv.y, sh.y));
        xv.z = fmaxf(0.f, fmaf(sc.z, xv.z, sh.z));
        xv.w = fmaxf(0.f, fmaf(sc.w, xv.w, sh.w));
        a.x = fmaf(w, xv.x, a.x);
        a.y = fmaf(w, xv.y, a.y);
        a.z = fmaf(w, xv.z, a.z);
        a.w = fmaf(w, xv.w, a.w);
    };

    int n = min(cnt[r], CAP);
    int base = r * CAP;
    float4 a0 = {0, 0, 0, 0}, a1 = a0, a2 = a0, a3 = a0;
    int k = g;
    for (; k + 3 * G < n; k += 4 * G) {
        proc(base + k, a0);
        proc(base + k + G, a1);
        proc(base + k + 2 * G, a2);
        proc(base + k + 3 * G, a3);
    }
    for (; k < n; k += G) proc(base + k, a0);

    float4 acc;
    acc.x = (a0.x + a1.x) + (a2.x + a3.x);
    acc.y = (a0.y + a1.y) + (a2.y + a3.y);
    acc.z = (a0.z + a1.z) + (a2.z + a3.z);
    acc.w = (a0.w + a1.w) + (a2.w + a3.w);
#pragma unroll
    for (int off = FQ; off < 32; off <<= 1) {
        acc.x += __shfl_xor_sync(0xffffffffu, acc.x, off);
        acc.y += __shfl_xor_sync(0xffffffffu, acc.y, off);
        acc.z += __shfl_xor_sync(0xffffffffu, acc.z, off);
        acc.w += __shfl_xor_sync(0xffffffffu, acc.w, off);
    }
    // all lanes now hold the full group-sum for their q; add BN'd self-loop + dr scaling
    float dr = g_dis[r];
    float4 xr = X4[r * FQ + q];
    xr.x = fmaxf(0.f, fmaf(sc.x, xr.x, sh.x));
    xr.y = fmaxf(0.f, fmaf(sc.y, xr.y, sh.y));
    xr.z = fmaxf(0.f, fmaf(sc.z, xr.z, sh.z));
    xr.w = fmaxf(0.f, fmaf(sc.w, xr.w, sh.w));
    float4 vfin;
    vfin.x = dr * fmaf(dr, xr.x, acc.x);
    vfin.y = dr * fmaf(dr, xr.y, acc.y);
    vfin.z = dr * fmaf(dr, xr.z, acc.z);
    vfin.w = dr * fmaf(dr, xr.w, acc.w);

    // dense FI->64: broadcast v across warp, each lane computes outputs (lane, lane+32)
    float z0 = 0.f, z1 = 0.f;
#pragma unroll
    for (int k4 = 0; k4 < FQ; k4++) {
        float4 vv;
        vv.x = __shfl_sync(0xffffffffu, vfin.x, k4);   // source lane k4 has q == k4
        vv.y = __shfl_sync(0xffffffffu, vfin.y, k4);
        vv.z = __shfl_sync(0xffffffffu, vfin.z, k4);
        vv.w = __shfl_sync(0xffffffffu, vfin.w, k4);
        int kk = 4 * k4;
        z0 = fmaf(vv.x, Ws[(kk + 0) * 64 + lane], z0);
        z0 = fmaf(vv.y, Ws[(kk + 1) * 64 + lane], z0);
        z0 = fmaf(vv.z, Ws[(kk + 2) * 64 + lane], z0);
        z0 = fmaf(vv.w, Ws[(kk + 3) * 64 + lane], z0);
        z1 = fmaf(vv.x, Ws[(kk + 0) * 64 + lane + 32], z1);
        z1 = fmaf(vv.y, Ws[(kk + 1) * 64 + lane + 32], z1);
        z1 = fmaf(vv.z, Ws[(kk + 2) * 64 + lane + 32], z1);
        z1 = fmaf(vv.w, Ws[(kk + 3) * 64 + lane + 32], z1);
    }
    Z[r * 64 + lane] = z0;
    Z[r * 64 + lane + 32] = z1;
    atomicAdd(&s_sum[lane], z0);
    atomicAdd(&s_sq[lane], z0 * z0);
    atomicAdd(&s_sum[lane + 32], z1);
    atomicAdd(&s_sq[lane + 32], z1 * z1);
    __syncthreads();
    if (tid < 64) {
        atomicAdd(&stout[tid], s_sum[tid]);
        atomicAdd(&stout[64 + tid], s_sq[tid]);
    }
}

// ---------------- BN3 + ReLU + two-stage per-graph max pool ----------------
__global__ void __launch_bounds__(256) k_pool(const float* __restrict__ Z,
                                              const int* __restrict__ batch,
                                              const float* __restrict__ bnst,
                                              const float* __restrict__ gamma,
                                              const float* __restrict__ beta,
                                              unsigned* __restrict__ embu) {
    int tid = threadIdx.x;
    int f = tid & 63;
    int sub = tid >> 6;                 // 0..3
    int node0 = blockIdx.x * 32;
    float su = bnst[f], sq = bnst[64 + f];
    float mu = su * INVN;
    float scv = gamma[f] * rsqrtf(sq * INVN - mu * mu + 1e-5f);
    float shv = fmaf(-mu, scv, beta[f]);
    int curb = batch[node0 + sub];
    float m = 0.f;                      // post-relu values >= 0; 0 also covers empty graphs
#pragma unroll
    for (int i = 0; i < 8; i++) {
        int node = node0 + sub + 4 * i;
        int b = batch[node];
        float v = fmaxf(0.f, fmaf(scv, Z[node * 64 + f], shv));
        if (b != curb) {
            atomicMax(&embu[curb * 64 + f], __float_as_uint(m));
            m = 0.f;
            curb = b;
        }
        m = fmaxf(m, v);
    }
    atomicMax(&embu[curb * 64 + f], __float_as_uint(m));
}

// ---------------- MLP layer: (r,j)-parallel, shuffle BN over 16 rows ----------------
template <int FI, int FO, bool CVT>
__global__ void __launch_bounds__(256) k_mlp(const void* __restrict__ Xin,
                                             const float* __restrict__ W,
                                             const float* __restrict__ gamma,
                                             const float* __restrict__ beta,
                                             float* __restrict__ Y,
                                             float* __restrict__ out, int out_size) {
    __shared__ float Xs[BB * FI];
    int tid = threadIdx.x;
    for (int i = tid; i < BB * FI; i += 256) {
        float v = CVT ? __uint_as_float(((const unsigned*)Xin)[i]) : ((const float*)Xin)[i];
        Xs[i] = v;
        if (CVT && blockIdx.x == 0) {
            int o = BB * 11 + i;
            if (o < out_size) out[o] = v;   // emb output
        }
    }
    __syncthreads();
    int r = tid & 15;
    int jl = tid >> 4;
    int j = blockIdx.x * 16 + jl;
    float acc = 0.f;
    for (int k = 0; k < FI; k++) acc = fmaf(Xs[r * FI + k], __ldg(W + k * FO + j), acc);
    float s = acc, s2 = acc * acc;
#pragma unroll
    for (int off = 1; off < 16; off <<= 1) {
        s  += __shfl_xor_sync(0xffffffffu, s, off);
        s2 += __shfl_xor_sync(0xffffffffu, s2, off);
    }
    float mu = s * (1.0f / BB);
    float var = s2 * (1.0f / BB) - mu * mu;
    float scv = gamma[j] * rsqrtf(var + 1e-5f);
    float shv = fmaf(-mu, scv, beta[j]);
    Y[r * FO + j] = fmaxf(0.f, fmaf(scv, acc, shv));
}

// ---------------- final linear + log_softmax ----------------
__global__ void k_head(const float* __restrict__ X, const float* __restrict__ W,
                       const float* __restrict__ bias, float* __restrict__ out, int out_size) {
    __shared__ float L[BB * 11];
    __shared__ float mrow[BB], lrow[BB];
    int tid = threadIdx.x;
    if (tid < BB * 11) {
        int r = tid / 11, c = tid % 11;
        float acc = bias[c];
        for (int k = 0; k < 256; k++) acc = fmaf(X[r * 256 + k], __ldg(W + k * 11 + c), acc);
        L[tid] = acc;
    }
    __syncthreads();
    if (tid < BB) {
        float m = -1e30f;
        for (int c = 0; c < 11; c++) m = fmaxf(m, L[tid * 11 + c]);
        float s = 0.f;
        for (int c = 0; c < 11; c++) s += expf(L[tid * 11 + c] - m);
        mrow[tid] = m;
        lrow[tid] = logf(s);
    }
    __syncthreads();
    if (tid < BB * 11 && tid < out_size) {
        int r = tid / 11;
        out[tid] = L[tid] - mrow[r] - lrow[r];
    }
}

// ---------------- launch ----------------
extern "C" void kernel_launch(void* const* d_in, const int* in_sizes, int n_in,
                              void* d_out, int out_size) {
    const float* x    = (const float*)d_in[0];
    const float* ea   = (const float*)d_in[1];
    const float* we   = (const float*)d_in[2];
    const float* be   = (const float*)d_in[3];
    const float* w1   = (const float*)d_in[4];
    const float* g1   = (const float*)d_in[6];
    const float* be1  = (const float*)d_in[7];
    const float* w2   = (const float*)d_in[8];
    const float* g2   = (const float*)d_in[10];
    const float* be2  = (const float*)d_in[11];
    const float* w3   = (const float*)d_in[12];
    const float* g3   = (const float*)d_in[14];
    const float* be3  = (const float*)d_in[15];
    const float* wf1  = (const float*)d_in[16];
    const float* gf1  = (const float*)d_in[18];
    const float* bef1 = (const float*)d_in[19];
    const float* wf2  = (const float*)d_in[20];
    const float* gf2  = (const float*)d_in[22];
    const float* bef2 = (const float*)d_in[23];
    const float* wf3  = (const float*)d_in[24];
    const float* bf3  = (const float*)d_in[25];
    const int*   ei   = (const int*)d_in[26];
    const int*   batch= (const int*)d_in[27];
    float* out = (float*)d_out;

    void *pz, *pa, *pb, *po1, *po2;
    cudaGetSymbolAddress(&pz, g_zb);
    cudaGetSymbolAddress(&pa, g_bufA);
    cudaGetSymbolAddress(&pb, g_bufB);
    cudaGetSymbolAddress(&po1, g_o1);
    cudaGetSymbolAddress(&po2, g_o2);
    unsigned* zb = (unsigned*)pz;
    float* degsum = (float*)zb;
    int* cnt = (int*)(zb + NN);
    float* stats = (float*)(zb + 2 * NN);          // S1@0, S2@128, S3@256 (sum@+0, sq@+64)
    unsigned* embu = zb + 2 * NN + 384;
    float* bufA = (float*)pa;
    float* bufB = (float*)pb;
    float* o1 = (float*)po1;
    float* o2 = (float*)po2;

    cudaMemsetAsync(pz, 0, sizeof(unsigned) * (2 * NN + 384 + BB * 64));
    k_edgexw1<<<EE / 256 + NN / 8, 256>>>(ea, we, be, ei, x, w1, degsum, cnt);
    k_dis<<<NN / 256, 256>>>(degsum);
    // layer 1: spmm over x@w1 (premultiplies weights for later layers), BN1 stats
    k_spmm1<<<NN / 8, 256>>>(bufA, bufB, cnt, stats);
    // layer 2: spmm(BN1+relu on load) fused with dense 32->64, BN2 stats
    k_sd<32><<<NN / 8, 256>>>(bufB, w2, bufA, cnt, stats, g1, be1, stats + 128);
    // layer 3: spmm(BN2+relu on load) fused with dense 64->64, BN3 stats
    k_sd<64><<<NN / 8, 256>>>(bufA, w3, bufB, cnt, stats + 128, g2, be2, stats + 256);
    // BN3 + relu + two-stage global max pool
    k_pool<<<NN / 32, 256>>>(bufB, batch, stats + 256, g3, be3, embu);
    // MLP head (emb conversion + emb output fused into mlp1)
    k_mlp<64, 512, true><<<32, 256>>>(embu, wf1, gf1, bef1, o1, out, out_size);
    k_mlp<512, 256, false><<<16, 256>>>(o1, wf2, gf2, bef2, o2, out, out_size);
    k_head<<<1, 192>>>(o2, wf3, bf3, out, out_size);
}